// round 4
// baseline (speedup 1.0000x reference)
#include <cuda_runtime.h>
#include <cstdint>
#include <cstddef>

// ---------------- problem constants ----------------
#define LSEQ 4096
#define INF  512
#define HID  512
#define G3   1536          // 3*HID gate rows
#define K1DIM (1024*9)     // 9216 : KAN1 fused K
#define K2DIM (512*9)      // 4608 : KAN2 fused K
#define BD   32            // persistent blocks per GRU direction
#define UPB  16            // units (warps) per GRU block

// ---------------- device scratch (allocation-free rule) ----------------
__device__ float d_gi_f[LSEQ * G3];
__device__ float d_gi_b[LSEQ * G3];
__device__ float d_xcat[LSEQ * 1024];          // [out_f | out_b], also KAN1 input
__device__ float d_F[(size_t)LSEQ * K1DIM];    // feature matrix (reused for layer 2)
__device__ float d_Wk1[K1DIM * 512];
__device__ float d_Wk2[K2DIM * 512];
__device__ float d_wihT_f[INF * G3];
__device__ float d_wihT_b[INF * G3];
__device__ float d_a2[LSEQ * 512];
// h broadcast values (parity double-buffered) + per-block monotonic flags
__device__ float    d_hval[2][2][HID];
__device__ unsigned d_flag[2][BD];

// ---------------- memory-order helpers ----------------
__device__ __forceinline__ unsigned ld_acq32(const unsigned* p) {
    unsigned v;
    asm volatile("ld.acquire.gpu.global.u32 %0, [%1];" : "=r"(v) : "l"(p) : "memory");
    return v;
}
__device__ __forceinline__ float ld_rlx_f32(const float* p) {
    float v;
    asm volatile("ld.relaxed.gpu.global.f32 %0, [%1];" : "=f"(v) : "l"(p) : "memory");
    return v;
}
__device__ __forceinline__ void st_rlx_f32(float* p, float v) {
    asm volatile("st.relaxed.gpu.global.f32 [%0], %1;" :: "l"(p), "f"(v) : "memory");
}
__device__ __forceinline__ void red_rel_add(unsigned* p) {
    asm volatile("red.release.gpu.global.add.u32 [%0], 1;" :: "l"(p) : "memory");
}

// ---------------- small prep kernels ----------------
__global__ void reset_sync_kernel() {
    int i = blockIdx.x * blockDim.x + threadIdx.x;
    if (i < 2 * BD) ((unsigned*)d_flag)[i] = 0u;
    if (i < 2 * 2 * HID) ((float*)d_hval)[i] = 0.0f;
}

// in: rows x cols (row-major)  ->  out: cols x rows (row-major)
__global__ void transpose_kernel(const float* __restrict__ in, float* __restrict__ out,
                                 int rows, int cols) {
    int idx = blockIdx.x * blockDim.x + threadIdx.x;
    if (idx < rows * cols) {
        int r = idx / cols, c = idx - r * cols;
        out[c * rows + r] = in[idx];
    }
}

// Pack KAN weights into Wk[k][o] with k = i*9 + j:
//   j==0 -> base_w[o][i], j>=1 -> spline_w[o][i][j-1] * scaler[o][i]
__global__ void pack_kan_kernel(const float* __restrict__ bw, const float* __restrict__ sw,
                                const float* __restrict__ sc, float* __restrict__ Wk,
                                int infeat) {
    int idx = blockIdx.x * blockDim.x + threadIdx.x;
    int total = infeat * 9 * 512;
    if (idx < total) {
        int o = idx & 511;
        int k = idx >> 9;
        int i = k / 9, j = k - i * 9;
        int oi = o * infeat + i;
        float v = (j == 0) ? bw[oi] : sw[(size_t)oi * 8 + (j - 1)] * sc[oi];
        Wk[idx] = v;
    }
}

// ---------------- KAN feature generation (silu + 8 cubic B-spline bases) ----------------
__device__ __forceinline__ void kan_feats(float x, float* out9) {
    const float hg = 2.0f / 5.0f;
    float t[12];
#pragma unroll
    for (int j = 0; j < 12; j++) t[j] = (float)(j - 3) * hg - 1.0f;
    float b[11];
#pragma unroll
    for (int j = 0; j < 11; j++) b[j] = (x >= t[j] && x < t[j + 1]) ? 1.0f : 0.0f;
#pragma unroll
    for (int k = 1; k <= 3; k++) {
#pragma unroll
        for (int j = 0; j + k < 11; j++) {
            b[j] = (x - t[j]) / (t[j + k] - t[j]) * b[j]
                 + (t[j + k + 1] - x) / (t[j + k + 1] - t[j + 1]) * b[j + 1];
        }
    }
    out9[0] = x / (1.0f + expf(-x));   // silu
#pragma unroll
    for (int j = 0; j < 8; j++) out9[1 + j] = b[j];
}

__global__ void featgen_kernel(const float* __restrict__ X, float* __restrict__ F, int total) {
    int idx = blockIdx.x * blockDim.x + threadIdx.x;
    if (idx < total) {
        float o9[9];
        kan_feats(X[idx], o9);
        float* dst = F + (size_t)idx * 9;
#pragma unroll
        for (int j = 0; j < 9; j++) dst[j] = o9[j];
    }
}

// ---------------- fp32 SGEMM: C[M,N] = A[M,K] @ B[K,N] (+bias) (+activation) ----------------
// BM=128, BN=64, BK=16, 256 threads, 8x4 per thread.
// mode: 0 = +bias, 1 = relu, 2 = sigmoid
__global__ __launch_bounds__(256) void sgemm_kernel(
    const float* __restrict__ A, const float* __restrict__ B, float* __restrict__ C,
    const float* __restrict__ bias, int M, int N, int K, int mode)
{
    __shared__ float As[16][128];
    __shared__ float Bs[16][64];
    int bx = blockIdx.x;   // N tile
    int by = blockIdx.y;   // M tile
    int tid = threadIdx.x;

    int arow = tid >> 1;
    int ak8  = (tid & 1) * 8;
    int brow = tid >> 4;
    int bcol = (tid & 15) * 4;

    const float* Ab = A + (size_t)(by * 128) * K;
    const float* Bb = B + bx * 64;

    int tm = (tid >> 4) * 8;   // 0..120
    int tn = (tid & 15) * 4;   // 0..60

    float acc[8][4];
#pragma unroll
    for (int i = 0; i < 8; i++)
#pragma unroll
        for (int j = 0; j < 4; j++) acc[i][j] = 0.0f;

    for (int k0 = 0; k0 < K; k0 += 16) {
        float4 a0 = *(const float4*)(Ab + (size_t)arow * K + k0 + ak8);
        float4 a1 = *(const float4*)(Ab + (size_t)arow * K + k0 + ak8 + 4);
        float4 bv = *(const float4*)(Bb + (size_t)(k0 + brow) * N + bcol);
        As[ak8 + 0][arow] = a0.x; As[ak8 + 1][arow] = a0.y;
        As[ak8 + 2][arow] = a0.z; As[ak8 + 3][arow] = a0.w;
        As[ak8 + 4][arow] = a1.x; As[ak8 + 5][arow] = a1.y;
        As[ak8 + 6][arow] = a1.z; As[ak8 + 7][arow] = a1.w;
        *(float4*)&Bs[brow][bcol] = bv;
        __syncthreads();
#pragma unroll
        for (int kk = 0; kk < 16; kk++) {
            float ar[8], br[4];
            float4 arv0 = *(const float4*)&As[kk][tm];
            float4 arv1 = *(const float4*)&As[kk][tm + 4];
            ar[0] = arv0.x; ar[1] = arv0.y; ar[2] = arv0.z; ar[3] = arv0.w;
            ar[4] = arv1.x; ar[5] = arv1.y; ar[6] = arv1.z; ar[7] = arv1.w;
            float4 brv = *(const float4*)&Bs[kk][tn];
            br[0] = brv.x; br[1] = brv.y; br[2] = brv.z; br[3] = brv.w;
#pragma unroll
            for (int i = 0; i < 8; i++)
#pragma unroll
                for (int j = 0; j < 4; j++)
                    acc[i][j] = fmaf(ar[i], br[j], acc[i][j]);
        }
        __syncthreads();
    }

#pragma unroll
    for (int i = 0; i < 8; i++) {
        int row = by * 128 + tm + i;
#pragma unroll
        for (int j = 0; j < 4; j++) {
            int col = bx * 64 + tn + j;
            float v = acc[i][j];
            if (bias) v += bias[col];
            if (mode == 1) v = fmaxf(v, 0.0f);
            else if (mode == 2) v = 1.0f / (1.0f + expf(-v));
            C[(size_t)row * N + col] = v;
        }
    }
}

// ---------------- fast activations (serial-path) ----------------
__device__ __forceinline__ float fast_sigmoid(float x) {
    return __fdividef(1.0f, 1.0f + __expf(-x));
}
__device__ __forceinline__ float fast_tanh(float x) {
    if (x >  15.0f) return  1.0f;
    if (x < -15.0f) return -1.0f;
    float t = __expf(2.0f * x);
    return __fdividef(t - 1.0f, t + 1.0f);
}

// ---------------- persistent bidirectional GRU recurrence ----------------
// 64 blocks (32 fwd, 32 bwd), 512 threads each. One warp = one hidden unit.
// W_hh rows register-resident. Handoff: lane0 st.relaxed h value, then
// red.release.add on per-block flag (+16/step). Only warp 0 spins (on 32
// flags, ld.acquire); data fetched once, coalesced, after detection.
__global__ __launch_bounds__(512, 1) void gru_kernel(
    const float* __restrict__ w_hh_f, const float* __restrict__ w_hh_b,
    const float* __restrict__ b_hh_f, const float* __restrict__ b_hh_b)
{
    int dir = (blockIdx.x >= BD) ? 1 : 0;
    int blk = blockIdx.x - dir * BD;
    const float* gi  = dir ? d_gi_b : d_gi_f;
    const float* whh = dir ? w_hh_b : w_hh_f;
    const float* bhh = dir ? b_hh_b : b_hh_f;
    float*    hv = &d_hval[dir][0][0];    // [parity][unit]
    unsigned* fl = &d_flag[dir][0];       // [block], monotonic, +16 per step

    int tid  = threadIdx.x;
    int lane = tid & 31;
    int w    = tid >> 5;
    int u    = blk * UPB + w;      // hidden unit this warp produces (0..511)
    int colbase = dir ? HID : 0;

    // register-resident recurrent weights for this unit's 3 gate rows
    float wr[16], wz[16], wn[16];
#pragma unroll
    for (int i = 0; i < 16; i++) {
        int k = lane + 32 * i;
        wr[i] = whh[(size_t)u * HID + k];
        wz[i] = whh[(size_t)(HID + u) * HID + k];
        wn[i] = whh[(size_t)(2 * HID + u) * HID + k];
    }
    float br = bhh[u], bz = bhh[HID + u], bn = bhh[2 * HID + u];
    float hp = 0.0f;   // lane0: previous h of unit u (register-resident)

    __shared__ float hsh[2][HID];   // ping-pong staging by step parity

    for (int s = 0; s < LSEQ; s++) {
        int t = dir ? (LSEQ - 1 - s) : s;
        int p = s & 1;

        // prefetch input gates early (independent of handoff)
        float ir = 0.f, iz = 0.f, inn = 0.f;
        if (lane == 0) {
            const float* g = gi + (size_t)t * G3 + u;
            ir = g[0]; iz = g[512]; inn = g[1024];
        }

        if (s == 0) {
            hsh[0][tid] = 0.0f;
            __syncthreads();
        } else {
            // warp 0 polls the 32 per-block flags (acquire); others wait at bar
            if (w == 0) {
                unsigned tgt = (unsigned)(s * UPB);
                const unsigned* fp = fl + lane;
                unsigned v;
                do { v = ld_acq32(fp); } while (v < tgt);
            }
            __syncthreads();
            // coalesced one-shot fetch of previous hidden state
            hsh[p][tid] = ld_rlx_f32(hv + (size_t)((s - 1) & 1) * HID + tid);
            __syncthreads();
        }

        // 3 dot products of length 512 (one unit per warp)
        float ar = 0.f, az = 0.f, an = 0.f;
#pragma unroll
        for (int i = 0; i < 16; i++) {
            float v = hsh[p][lane + 32 * i];
            ar = fmaf(wr[i], v, ar);
            az = fmaf(wz[i], v, az);
            an = fmaf(wn[i], v, an);
        }
#pragma unroll
        for (int off = 16; off; off >>= 1) {
            ar += __shfl_xor_sync(0xffffffffu, ar, off);
            az += __shfl_xor_sync(0xffffffffu, az, off);
            an += __shfl_xor_sync(0xffffffffu, an, off);
        }

        if (lane == 0) {
            float r = fast_sigmoid(ir + ar + br);
            float z = fast_sigmoid(iz + az + bz);
            float n = fast_tanh(inn + r * (an + bn));
            float hn = (1.0f - z) * n + z * hp;
            hp = hn;
            st_rlx_f32(hv + (size_t)p * HID + u, hn);   // publish value
            red_rel_add(fl + blk);                      // then release-signal
            d_xcat[(size_t)t * 1024 + colbase + u] = hn;
        }
        // no trailing syncthreads: next iteration's two bars + parity ping-pong
        // plus flag-gated cross-block progress make reuse safe
    }
}

// ---------------- y[o] = sum_n a2[n][o] * p[n] ----------------
__global__ void colreduce_kernel(const float* __restrict__ A, const float* __restrict__ p,
                                 float* __restrict__ y) {
    int o = blockIdx.x * blockDim.x + threadIdx.x;   // 0..511
    float acc = 0.0f;
#pragma unroll 8
    for (int n = 0; n < LSEQ; n++)
        acc = fmaf(A[(size_t)n * 512 + o], p[n], acc);
    y[o] = acc;
}

// ---------------- launch ----------------
extern "C" void kernel_launch(void* const* d_in, const int* in_sizes, int n_in,
                              void* d_out, int out_size) {
    const float* h        = (const float*)d_in[0];
    const float* p        = (const float*)d_in[1];
    const float* w_ih_f   = (const float*)d_in[2];
    const float* w_hh_f   = (const float*)d_in[3];
    const float* b_ih_f   = (const float*)d_in[4];
    const float* b_hh_f   = (const float*)d_in[5];
    const float* w_ih_b   = (const float*)d_in[6];
    const float* w_hh_b   = (const float*)d_in[7];
    const float* b_ih_b   = (const float*)d_in[8];
    const float* b_hh_b   = (const float*)d_in[9];
    const float* base_w1  = (const float*)d_in[10];
    const float* spline_w1= (const float*)d_in[11];
    const float* scaler1  = (const float*)d_in[12];
    const float* base_w2  = (const float*)d_in[13];
    const float* spline_w2= (const float*)d_in[14];
    const float* scaler2  = (const float*)d_in[15];
    float* out = (float*)d_out;

    float *p_gi_f, *p_gi_b, *p_xcat, *p_F, *p_Wk1, *p_Wk2, *p_wihT_f, *p_wihT_b, *p_a2;
    cudaGetSymbolAddress((void**)&p_gi_f,   d_gi_f);
    cudaGetSymbolAddress((void**)&p_gi_b,   d_gi_b);
    cudaGetSymbolAddress((void**)&p_xcat,   d_xcat);
    cudaGetSymbolAddress((void**)&p_F,      d_F);
    cudaGetSymbolAddress((void**)&p_Wk1,    d_Wk1);
    cudaGetSymbolAddress((void**)&p_Wk2,    d_Wk2);
    cudaGetSymbolAddress((void**)&p_wihT_f, d_wihT_f);
    cudaGetSymbolAddress((void**)&p_wihT_b, d_wihT_b);
    cudaGetSymbolAddress((void**)&p_a2,     d_a2);

    // launch order chosen so ncu (-s 5 -c 1) profiles gru_kernel (launch #5)

    // 0. reset flags + h buffer (deterministic across graph replays)
    reset_sync_kernel<<<8, 256>>>();

    // 1,2. transpose input-gate weight matrices (1536x512 -> 512x1536)
    {
        int total = G3 * INF;
        transpose_kernel<<<(total + 255) / 256, 256>>>(w_ih_f, p_wihT_f, G3, INF);
        transpose_kernel<<<(total + 255) / 256, 256>>>(w_ih_b, p_wihT_b, G3, INF);
    }

    // 3,4. input-gate GEMMs: gi = h @ w_ih^T + b_ih   (4096 x 1536)
    {
        dim3 grid(G3 / 64, LSEQ / 128);
        sgemm_kernel<<<grid, 256>>>(h, p_wihT_f, p_gi_f, b_ih_f, LSEQ, G3, INF, 0);
        sgemm_kernel<<<grid, 256>>>(h, p_wihT_b, p_gi_b, b_ih_b, LSEQ, G3, INF, 0);
    }

    // 5. persistent bidirectional recurrence -> d_xcat (4096 x 1024)
    gru_kernel<<<2 * BD, 512>>>(w_hh_f, w_hh_b, b_hh_f, b_hh_b);

    // 6,7. pack KAN weights (moved after GRU; only needed by KAN GEMMs)
    {
        int t1 = 1024 * 9 * 512;
        int t2 = 512 * 9 * 512;
        pack_kan_kernel<<<(t1 + 255) / 256, 256>>>(base_w1, spline_w1, scaler1, p_Wk1, 1024);
        pack_kan_kernel<<<(t2 + 255) / 256, 256>>>(base_w2, spline_w2, scaler2, p_Wk2, 512);
    }

    // 8,9. KAN layer 1: features of xcat -> GEMM (+relu) -> a_1 (stored in d_out+512)
    {
        int total = LSEQ * 1024;
        featgen_kernel<<<(total + 255) / 256, 256>>>(p_xcat, p_F, total);
        dim3 grid(512 / 64, LSEQ / 128);
        sgemm_kernel<<<grid, 256>>>(p_F, p_Wk1, out + 512, nullptr, LSEQ, 512, K1DIM, 1);
    }

    // 10,11. KAN layer 2: features of a_1 -> GEMM (+sigmoid) -> a_2
    {
        int total = LSEQ * 512;
        featgen_kernel<<<(total + 255) / 256, 256>>>(out + 512, p_F, total);
        dim3 grid(512 / 64, LSEQ / 128);
        sgemm_kernel<<<grid, 256>>>(p_F, p_Wk2, p_a2, nullptr, LSEQ, 512, K2DIM, 2);
    }

    // 12. y = a_2^T @ p  (512,)
    colreduce_kernel<<<4, 128>>>(p_a2, p, out);
}

// round 5
// speedup vs baseline: 1.3887x; 1.3887x over previous
#include <cuda_runtime.h>
#include <cstdint>
#include <cstddef>

// ---------------- problem constants ----------------
#define LSEQ 4096
#define INF  512
#define HID  512
#define G3   1536          // 3*HID gate rows
#define K1DIM (1024*9)     // 9216 : KAN1 fused K
#define K2DIM (512*9)      // 4608 : KAN2 fused K
#define BD   32            // persistent blocks per GRU direction
#define UPB  16            // units (warps) per GRU block

// ---------------- device scratch (allocation-free rule) ----------------
__device__ float d_gi_f[LSEQ * G3];
__device__ float d_gi_b[LSEQ * G3];
__device__ float d_xcat[LSEQ * 1024];          // [out_f | out_b], also KAN1 input
__device__ float d_F[(size_t)LSEQ * K1DIM];    // feature matrix (reused for layer 2)
__device__ float d_Wk1[K1DIM * 512];
__device__ float d_Wk2[K2DIM * 512];
__device__ float d_wihT_f[INF * G3];
__device__ float d_wihT_b[INF * G3];
__device__ float d_a2[LSEQ * 512];
// tagged h-broadcast buffer: [dir][parity][unit] = (tag<<32)|bits(h)
__device__ unsigned long long d_hbuf[2][2][HID];

// ---------------- relaxed global ld/st helpers ----------------
__device__ __forceinline__ void ld_rlx_v2_u64(const unsigned long long* p,
                                              unsigned long long& a, unsigned long long& b) {
    asm volatile("ld.relaxed.gpu.global.v2.u64 {%0, %1}, [%2];"
                 : "=l"(a), "=l"(b) : "l"(p) : "memory");
}
__device__ __forceinline__ void st_rlx64(unsigned long long* p, unsigned long long v) {
    asm volatile("st.relaxed.gpu.global.u64 [%0], %1;" :: "l"(p), "l"(v) : "memory");
}

// ---------------- combined prep: reset hbuf + both weight transposes ----------------
// idx < NT: transpose w_ih_f; idx in [NT, 2NT): transpose w_ih_b.
// first 2048 threads also reset d_hbuf.
__global__ void prep_kernel(const float* __restrict__ wf, const float* __restrict__ wb,
                            float* __restrict__ of, float* __restrict__ ob) {
    int idx = blockIdx.x * blockDim.x + threadIdx.x;
    const int NT = G3 * INF;
    if (idx < 2 * 2 * HID) ((unsigned long long*)d_hbuf)[idx] = 0ull;
    if (idx < NT) {
        int r = idx / INF, c = idx - r * INF;        // in: (G3 x INF)
        of[c * G3 + r] = wf[idx];
    } else if (idx < 2 * NT) {
        int j = idx - NT;
        int r = j / INF, c = j - r * INF;
        ob[c * G3 + r] = wb[j];
    }
}

// Pack KAN weights into Wk[k][o] with k = i*9 + j:
//   j==0 -> base_w[o][i], j>=1 -> spline_w[o][i][j-1] * scaler[o][i]
__global__ void pack_kan_kernel(const float* __restrict__ bw, const float* __restrict__ sw,
                                const float* __restrict__ sc, float* __restrict__ Wk,
                                int infeat) {
    int idx = blockIdx.x * blockDim.x + threadIdx.x;
    int total = infeat * 9 * 512;
    if (idx < total) {
        int o = idx & 511;
        int k = idx >> 9;
        int i = k / 9, j = k - i * 9;
        int oi = o * infeat + i;
        float v = (j == 0) ? bw[oi] : sw[(size_t)oi * 8 + (j - 1)] * sc[oi];
        Wk[idx] = v;
    }
}

// ---------------- KAN feature generation (silu + 8 cubic B-spline bases) ----------------
__device__ __forceinline__ void kan_feats(float x, float* out9) {
    const float hg = 2.0f / 5.0f;
    float t[12];
#pragma unroll
    for (int j = 0; j < 12; j++) t[j] = (float)(j - 3) * hg - 1.0f;
    float b[11];
#pragma unroll
    for (int j = 0; j < 11; j++) b[j] = (x >= t[j] && x < t[j + 1]) ? 1.0f : 0.0f;
#pragma unroll
    for (int k = 1; k <= 3; k++) {
#pragma unroll
        for (int j = 0; j + k < 11; j++) {
            b[j] = (x - t[j]) / (t[j + k] - t[j]) * b[j]
                 + (t[j + k + 1] - x) / (t[j + k + 1] - t[j + 1]) * b[j + 1];
        }
    }
    out9[0] = x / (1.0f + expf(-x));   // silu
#pragma unroll
    for (int j = 0; j < 8; j++) out9[1 + j] = b[j];
}

__global__ void featgen_kernel(const float* __restrict__ X, float* __restrict__ F, int total) {
    int idx = blockIdx.x * blockDim.x + threadIdx.x;
    if (idx < total) {
        float o9[9];
        kan_feats(X[idx], o9);
        float* dst = F + (size_t)idx * 9;
#pragma unroll
        for (int j = 0; j < 9; j++) dst[j] = o9[j];
    }
}

// ---------------- fp32 SGEMM: C[M,N] = A[M,K] @ B[K,N] (+bias) (+activation) ----------------
// BM=128, BN=64, BK=16, 256 threads, 8x4 per thread.
// mode: 0 = +bias, 1 = relu, 2 = sigmoid
__global__ __launch_bounds__(256) void sgemm_kernel(
    const float* __restrict__ A, const float* __restrict__ B, float* __restrict__ C,
    const float* __restrict__ bias, int M, int N, int K, int mode)
{
    __shared__ float As[16][128];
    __shared__ float Bs[16][64];
    int bx = blockIdx.x;   // N tile
    int by = blockIdx.y;   // M tile
    int tid = threadIdx.x;

    int arow = tid >> 1;
    int ak8  = (tid & 1) * 8;
    int brow = tid >> 4;
    int bcol = (tid & 15) * 4;

    const float* Ab = A + (size_t)(by * 128) * K;
    const float* Bb = B + bx * 64;

    int tm = (tid >> 4) * 8;   // 0..120
    int tn = (tid & 15) * 4;   // 0..60

    float acc[8][4];
#pragma unroll
    for (int i = 0; i < 8; i++)
#pragma unroll
        for (int j = 0; j < 4; j++) acc[i][j] = 0.0f;

    for (int k0 = 0; k0 < K; k0 += 16) {
        float4 a0 = *(const float4*)(Ab + (size_t)arow * K + k0 + ak8);
        float4 a1 = *(const float4*)(Ab + (size_t)arow * K + k0 + ak8 + 4);
        float4 bv = *(const float4*)(Bb + (size_t)(k0 + brow) * N + bcol);
        As[ak8 + 0][arow] = a0.x; As[ak8 + 1][arow] = a0.y;
        As[ak8 + 2][arow] = a0.z; As[ak8 + 3][arow] = a0.w;
        As[ak8 + 4][arow] = a1.x; As[ak8 + 5][arow] = a1.y;
        As[ak8 + 6][arow] = a1.z; As[ak8 + 7][arow] = a1.w;
        *(float4*)&Bs[brow][bcol] = bv;
        __syncthreads();
#pragma unroll
        for (int kk = 0; kk < 16; kk++) {
            float ar[8], br[4];
            float4 arv0 = *(const float4*)&As[kk][tm];
            float4 arv1 = *(const float4*)&As[kk][tm + 4];
            ar[0] = arv0.x; ar[1] = arv0.y; ar[2] = arv0.z; ar[3] = arv0.w;
            ar[4] = arv1.x; ar[5] = arv1.y; ar[6] = arv1.z; ar[7] = arv1.w;
            float4 brv = *(const float4*)&Bs[kk][tn];
            br[0] = brv.x; br[1] = brv.y; br[2] = brv.z; br[3] = brv.w;
#pragma unroll
            for (int i = 0; i < 8; i++)
#pragma unroll
                for (int j = 0; j < 4; j++)
                    acc[i][j] = fmaf(ar[i], br[j], acc[i][j]);
        }
        __syncthreads();
    }

#pragma unroll
    for (int i = 0; i < 8; i++) {
        int row = by * 128 + tm + i;
#pragma unroll
        for (int j = 0; j < 4; j++) {
            int col = bx * 64 + tn + j;
            float v = acc[i][j];
            if (bias) v += bias[col];
            if (mode == 1) v = fmaxf(v, 0.0f);
            else if (mode == 2) v = 1.0f / (1.0f + expf(-v));
            C[(size_t)row * N + col] = v;
        }
    }
}

// ---------------- fast activations (serial-path) ----------------
__device__ __forceinline__ float fast_sigmoid(float x) {
    return __fdividef(1.0f, 1.0f + __expf(-x));
}
__device__ __forceinline__ float fast_tanh(float x) {
    if (x >  15.0f) return  1.0f;
    if (x < -15.0f) return -1.0f;
    float t = __expf(2.0f * x);
    return __fdividef(t - 1.0f, t + 1.0f);
}

// ---------------- persistent bidirectional GRU recurrence ----------------
// 64 blocks (32 fwd, 32 bwd), 512 threads each. One warp = one hidden unit.
// W_hh rows register-resident. Handoff: tagged 8-byte payloads through L2
// (detection == delivery). Only warps 0-7 poll; each thread polls 2 adjacent
// units with one 16B ld.relaxed.v2.u64. Warps 8-15 wait at the barrier.
__global__ __launch_bounds__(512, 1) void gru_kernel(
    const float* __restrict__ w_hh_f, const float* __restrict__ w_hh_b,
    const float* __restrict__ b_hh_f, const float* __restrict__ b_hh_b)
{
    int dir = (blockIdx.x >= BD) ? 1 : 0;
    int blk = blockIdx.x - dir * BD;
    const float* gi  = dir ? d_gi_b : d_gi_f;
    const float* whh = dir ? w_hh_b : w_hh_f;
    const float* bhh = dir ? b_hh_b : b_hh_f;
    unsigned long long* hb = &d_hbuf[dir][0][0];   // [parity][unit]

    int tid  = threadIdx.x;
    int lane = tid & 31;
    int w    = tid >> 5;
    int u    = blk * UPB + w;      // hidden unit this warp produces (0..511)
    int colbase = dir ? HID : 0;

    // register-resident recurrent weights for this unit's 3 gate rows
    float wr[16], wz[16], wn[16];
#pragma unroll
    for (int i = 0; i < 16; i++) {
        int k = lane + 32 * i;
        wr[i] = whh[(size_t)u * HID + k];
        wz[i] = whh[(size_t)(HID + u) * HID + k];
        wn[i] = whh[(size_t)(2 * HID + u) * HID + k];
    }
    float br = bhh[u], bz = bhh[HID + u], bn = bhh[2 * HID + u];
    float hp = 0.0f;   // lane0: previous h of unit u (register-resident)

    __shared__ float hsh[2][HID];   // ping-pong staging by step parity

    for (int s = 0; s < LSEQ; s++) {
        int t = dir ? (LSEQ - 1 - s) : s;
        int p = s & 1;

        // prefetch input gates early (independent of handoff)
        float ir = 0.f, iz = 0.f, inn = 0.f;
        if (lane == 0) {
            const float* g = gi + (size_t)t * G3 + u;
            ir = g[0]; iz = g[512]; inn = g[1024];
        }

        if (s == 0) {
            hsh[0][tid] = 0.0f;
        } else if (w < 8) {
            // poll 2 adjacent tagged slots: detection == delivery
            int j = (w * 32 + lane) * 2;   // 0,2,..,1022
            const unsigned long long* slot = hb + (size_t)((s - 1) & 1) * HID + j;
            unsigned long long va, vb;
            unsigned tag = (unsigned)s;
            do { ld_rlx_v2_u64(slot, va, vb); }
            while ((unsigned)(va >> 32) != tag || (unsigned)(vb >> 32) != tag);
            hsh[p][j]     = __uint_as_float((unsigned)va);
            hsh[p][j + 1] = __uint_as_float((unsigned)vb);
        }
        __syncthreads();

        // 3 dot products of length 512 (one unit per warp)
        float ar = 0.f, az = 0.f, an = 0.f;
#pragma unroll
        for (int i = 0; i < 16; i++) {
            float v = hsh[p][lane + 32 * i];
            ar = fmaf(wr[i], v, ar);
            az = fmaf(wz[i], v, az);
            an = fmaf(wn[i], v, an);
        }
#pragma unroll
        for (int off = 16; off; off >>= 1) {
            ar += __shfl_xor_sync(0xffffffffu, ar, off);
            az += __shfl_xor_sync(0xffffffffu, az, off);
            an += __shfl_xor_sync(0xffffffffu, an, off);
        }

        if (lane == 0) {
            float r = fast_sigmoid(ir + ar + br);
            float z = fast_sigmoid(iz + az + bz);
            float n = fast_tanh(inn + r * (an + bn));
            float hn = (1.0f - z) * n + z * hp;
            hp = hn;
            // publish: tag s+1 + value in one atomic 8-byte relaxed store
            unsigned long long pay =
                ((unsigned long long)(unsigned)(s + 1) << 32) | (unsigned long long)__float_as_uint(hn);
            st_rlx64(hb + (size_t)p * HID + u, pay);
            d_xcat[(size_t)t * 1024 + colbase + u] = hn;
        }
        // no trailing syncthreads: leading bar + parity ping-pong + tag-gated
        // cross-block progress make smem reuse safe
    }
}

// ---------------- y[o] = sum_n a2[n][o] * p[n] ----------------
__global__ void colreduce_kernel(const float* __restrict__ A, const float* __restrict__ p,
                                 float* __restrict__ y) {
    int o = blockIdx.x * blockDim.x + threadIdx.x;   // 0..511
    float acc = 0.0f;
#pragma unroll 8
    for (int n = 0; n < LSEQ; n++)
        acc = fmaf(A[(size_t)n * 512 + o], p[n], acc);
    y[o] = acc;
}

// ---------------- launch ----------------
extern "C" void kernel_launch(void* const* d_in, const int* in_sizes, int n_in,
                              void* d_out, int out_size) {
    const float* h        = (const float*)d_in[0];
    const float* p        = (const float*)d_in[1];
    const float* w_ih_f   = (const float*)d_in[2];
    const float* w_hh_f   = (const float*)d_in[3];
    const float* b_ih_f   = (const float*)d_in[4];
    const float* b_hh_f   = (const float*)d_in[5];
    const float* w_ih_b   = (const float*)d_in[6];
    const float* w_hh_b   = (const float*)d_in[7];
    const float* b_ih_b   = (const float*)d_in[8];
    const float* b_hh_b   = (const float*)d_in[9];
    const float* base_w1  = (const float*)d_in[10];
    const float* spline_w1= (const float*)d_in[11];
    const float* scaler1  = (const float*)d_in[12];
    const float* base_w2  = (const float*)d_in[13];
    const float* spline_w2= (const float*)d_in[14];
    const float* scaler2  = (const float*)d_in[15];
    float* out = (float*)d_out;

    float *p_gi_f, *p_gi_b, *p_xcat, *p_F, *p_Wk1, *p_Wk2, *p_wihT_f, *p_wihT_b, *p_a2;
    cudaGetSymbolAddress((void**)&p_gi_f,   d_gi_f);
    cudaGetSymbolAddress((void**)&p_gi_b,   d_gi_b);
    cudaGetSymbolAddress((void**)&p_xcat,   d_xcat);
    cudaGetSymbolAddress((void**)&p_F,      d_F);
    cudaGetSymbolAddress((void**)&p_Wk1,    d_Wk1);
    cudaGetSymbolAddress((void**)&p_Wk2,    d_Wk2);
    cudaGetSymbolAddress((void**)&p_wihT_f, d_wihT_f);
    cudaGetSymbolAddress((void**)&p_wihT_b, d_wihT_b);
    cudaGetSymbolAddress((void**)&p_a2,     d_a2);

    // launch order arranged so ncu profiles launch index 4 == gru_kernel

    // 0. combined prep: reset hbuf + transpose both input-gate weight matrices
    {
        int total = 2 * G3 * INF;
        prep_kernel<<<(total + 255) / 256, 256>>>(w_ih_f, w_ih_b, p_wihT_f, p_wihT_b);
    }

    // 1,2. input-gate GEMMs: gi = h @ w_ih^T + b_ih   (4096 x 1536)
    {
        dim3 grid(G3 / 64, LSEQ / 128);
        sgemm_kernel<<<grid, 256>>>(h, p_wihT_f, p_gi_f, b_ih_f, LSEQ, G3, INF, 0);
        sgemm_kernel<<<grid, 256>>>(h, p_wihT_b, p_gi_b, b_ih_b, LSEQ, G3, INF, 0);
    }

    // 3. pack KAN1 weights (independent; placed here so gru is launch #4)
    {
        int t1 = 1024 * 9 * 512;
        pack_kan_kernel<<<(t1 + 255) / 256, 256>>>(base_w1, spline_w1, scaler1, p_Wk1, 1024);
    }

    // 4. persistent bidirectional recurrence -> d_xcat (4096 x 1024)   [ncu target]
    gru_kernel<<<2 * BD, 512>>>(w_hh_f, w_hh_b, b_hh_f, b_hh_b);

    // 5. pack KAN2 weights
    {
        int t2 = 512 * 9 * 512;
        pack_kan_kernel<<<(t2 + 255) / 256, 256>>>(base_w2, spline_w2, scaler2, p_Wk2, 512);
    }

    // 6,7. KAN layer 1: features of xcat -> GEMM (+relu) -> a_1 (stored in d_out+512)
    {
        int total = LSEQ * 1024;
        featgen_kernel<<<(total + 255) / 256, 256>>>(p_xcat, p_F, total);
        dim3 grid(512 / 64, LSEQ / 128);
        sgemm_kernel<<<grid, 256>>>(p_F, p_Wk1, out + 512, nullptr, LSEQ, 512, K1DIM, 1);
    }

    // 8,9. KAN layer 2: features of a_1 -> GEMM (+sigmoid) -> a_2
    {
        int total = LSEQ * 512;
        featgen_kernel<<<(total + 255) / 256, 256>>>(out + 512, p_F, total);
        dim3 grid(512 / 64, LSEQ / 128);
        sgemm_kernel<<<grid, 256>>>(p_F, p_Wk2, p_a2, nullptr, LSEQ, 512, K2DIM, 2);
    }

    // 10. y = a_2^T @ p  (512,)
    colreduce_kernel<<<4, 128>>>(p_a2, p, out);
}

// round 6
// speedup vs baseline: 1.5395x; 1.1086x over previous
#include <cuda_runtime.h>
#include <cstdint>
#include <cstddef>

// ---------------- problem constants ----------------
#define LSEQ 4096
#define INF  512
#define HID  512
#define G3   1536          // 3*HID gate rows
#define K1DIM (1024*9)     // 9216 : KAN1 fused K
#define K2DIM (512*9)      // 4608 : KAN2 fused K
#define BD   32            // persistent blocks per GRU direction
#define UPB  16            // units (warps) per GRU block

// ---------------- device scratch (allocation-free rule) ----------------
__device__ float d_gi_f[LSEQ * G3];
__device__ float d_gi_b[LSEQ * G3];
__device__ float d_xcat[LSEQ * 1024];          // [out_f | out_b], also KAN1 input
__device__ float d_F[(size_t)LSEQ * K1DIM];    // feature matrix (reused for layer 2)
__device__ float d_Wk1[K1DIM * 512];
__device__ float d_Wk2[K2DIM * 512];
__device__ float d_wihT_f[INF * G3];
__device__ float d_wihT_b[INF * G3];
__device__ float d_a2[LSEQ * 512];
// tagged h-broadcast buffer: [dir][parity][unit] = (tag<<32)|bits(h)
__device__ unsigned long long d_hbuf[2][2][HID];

// ---------------- relaxed global ld/st helpers ----------------
__device__ __forceinline__ void ld_rlx_v2_u64(const unsigned long long* p,
                                              unsigned long long& a, unsigned long long& b) {
    asm volatile("ld.relaxed.gpu.global.v2.u64 {%0, %1}, [%2];"
                 : "=l"(a), "=l"(b) : "l"(p) : "memory");
}
__device__ __forceinline__ void st_rlx64(unsigned long long* p, unsigned long long v) {
    asm volatile("st.relaxed.gpu.global.u64 [%0], %1;" :: "l"(p), "l"(v) : "memory");
}

// ---------------- combined prep: reset hbuf + both weight transposes ----------------
__global__ void prep_kernel(const float* __restrict__ wf, const float* __restrict__ wb,
                            float* __restrict__ of, float* __restrict__ ob) {
    int idx = blockIdx.x * blockDim.x + threadIdx.x;
    const int NT = G3 * INF;
    if (idx < 2 * 2 * HID) ((unsigned long long*)d_hbuf)[idx] = 0ull;
    if (idx < NT) {
        int r = idx / INF, c = idx - r * INF;        // in: (G3 x INF)
        of[c * G3 + r] = wf[idx];
    } else if (idx < 2 * NT) {
        int j = idx - NT;
        int r = j / INF, c = j - r * INF;
        ob[c * G3 + r] = wb[j];
    }
}

// Pack KAN weights into Wk[k][o] with k = i*9 + j:
//   j==0 -> base_w[o][i], j>=1 -> spline_w[o][i][j-1] * scaler[o][i]
__global__ void pack_kan_kernel(const float* __restrict__ bw, const float* __restrict__ sw,
                                const float* __restrict__ sc, float* __restrict__ Wk,
                                int infeat) {
    int idx = blockIdx.x * blockDim.x + threadIdx.x;
    int total = infeat * 9 * 512;
    if (idx < total) {
        int o = idx & 511;
        int k = idx >> 9;
        int i = k / 9, j = k - i * 9;
        int oi = o * infeat + i;
        float v = (j == 0) ? bw[oi] : sw[(size_t)oi * 8 + (j - 1)] * sc[oi];
        Wk[idx] = v;
    }
}

// ---------------- KAN feature generation (silu + 8 cubic B-spline bases) ----------------
__device__ __forceinline__ void kan_feats(float x, float* out9) {
    const float hg = 2.0f / 5.0f;
    float t[12];
#pragma unroll
    for (int j = 0; j < 12; j++) t[j] = (float)(j - 3) * hg - 1.0f;
    float b[11];
#pragma unroll
    for (int j = 0; j < 11; j++) b[j] = (x >= t[j] && x < t[j + 1]) ? 1.0f : 0.0f;
#pragma unroll
    for (int k = 1; k <= 3; k++) {
#pragma unroll
        for (int j = 0; j + k < 11; j++) {
            b[j] = (x - t[j]) / (t[j + k] - t[j]) * b[j]
                 + (t[j + k + 1] - x) / (t[j + k + 1] - t[j + 1]) * b[j + 1];
        }
    }
    out9[0] = x / (1.0f + expf(-x));   // silu
#pragma unroll
    for (int j = 0; j < 8; j++) out9[1 + j] = b[j];
}

__global__ void featgen_kernel(const float* __restrict__ X, float* __restrict__ F, int total) {
    int idx = blockIdx.x * blockDim.x + threadIdx.x;
    if (idx < total) {
        float o9[9];
        kan_feats(X[idx], o9);
        float* dst = F + (size_t)idx * 9;
#pragma unroll
        for (int j = 0; j < 9; j++) dst[j] = o9[j];
    }
}

// ---------------- fp32 SGEMM, 2-stage double-buffered ----------------
// C[M,N] = A[M,K] @ B[K,N] (+bias) (+activation)
// BM=128, BN=64, BK=16, 256 threads, 8x4 per thread.
// mode: 0 = +bias, 1 = relu, 2 = sigmoid
__global__ __launch_bounds__(256) void sgemm_kernel(
    const float* __restrict__ A, const float* __restrict__ B, float* __restrict__ C,
    const float* __restrict__ bias, int M, int N, int K, int mode)
{
    __shared__ float As[2][16][128];
    __shared__ float Bs[2][16][64];
    int bx = blockIdx.x;   // N tile
    int by = blockIdx.y;   // M tile
    int tid = threadIdx.x;

    int arow = tid >> 1;
    int ak8  = (tid & 1) * 8;
    int brow = tid >> 4;
    int bcol = (tid & 15) * 4;

    const float* Ap = A + (size_t)(by * 128 + arow) * K + ak8;
    const float* Bb = B + bx * 64;

    int tm = (tid >> 4) * 8;   // 0..120
    int tn = (tid & 15) * 4;   // 0..60

    float acc[8][4];
#pragma unroll
    for (int i = 0; i < 8; i++)
#pragma unroll
        for (int j = 0; j < 4; j++) acc[i][j] = 0.0f;

    // preload tile 0 into stage 0
    {
        float4 a0 = *(const float4*)(Ap);
        float4 a1 = *(const float4*)(Ap + 4);
        float4 bv = *(const float4*)(Bb + (size_t)brow * N + bcol);
        As[0][ak8 + 0][arow] = a0.x; As[0][ak8 + 1][arow] = a0.y;
        As[0][ak8 + 2][arow] = a0.z; As[0][ak8 + 3][arow] = a0.w;
        As[0][ak8 + 4][arow] = a1.x; As[0][ak8 + 5][arow] = a1.y;
        As[0][ak8 + 6][arow] = a1.z; As[0][ak8 + 7][arow] = a1.w;
        *(float4*)&Bs[0][brow][bcol] = bv;
    }
    __syncthreads();

    int ntiles = K >> 4;
    for (int kt = 0; kt < ntiles; kt++) {
        int cur = kt & 1;
        // issue global loads for next tile (overlap with compute below)
        float4 na0, na1, nbv;
        bool more = (kt + 1 < ntiles);
        if (more) {
            int k0 = (kt + 1) << 4;
            na0 = *(const float4*)(Ap + k0);
            na1 = *(const float4*)(Ap + k0 + 4);
            nbv = *(const float4*)(Bb + (size_t)(k0 + brow) * N + bcol);
        }
#pragma unroll
        for (int kk = 0; kk < 16; kk++) {
            float ar[8], br[4];
            float4 arv0 = *(const float4*)&As[cur][kk][tm];
            float4 arv1 = *(const float4*)&As[cur][kk][tm + 4];
            ar[0] = arv0.x; ar[1] = arv0.y; ar[2] = arv0.z; ar[3] = arv0.w;
            ar[4] = arv1.x; ar[5] = arv1.y; ar[6] = arv1.z; ar[7] = arv1.w;
            float4 brv = *(const float4*)&Bs[cur][kk][tn];
            br[0] = brv.x; br[1] = brv.y; br[2] = brv.z; br[3] = brv.w;
#pragma unroll
            for (int i = 0; i < 8; i++)
#pragma unroll
                for (int j = 0; j < 4; j++)
                    acc[i][j] = fmaf(ar[i], br[j], acc[i][j]);
        }
        if (more) {
            int nxt = cur ^ 1;
            As[nxt][ak8 + 0][arow] = na0.x; As[nxt][ak8 + 1][arow] = na0.y;
            As[nxt][ak8 + 2][arow] = na0.z; As[nxt][ak8 + 3][arow] = na0.w;
            As[nxt][ak8 + 4][arow] = na1.x; As[nxt][ak8 + 5][arow] = na1.y;
            As[nxt][ak8 + 6][arow] = na1.z; As[nxt][ak8 + 7][arow] = na1.w;
            *(float4*)&Bs[nxt][brow][bcol] = nbv;
        }
        __syncthreads();
    }

#pragma unroll
    for (int i = 0; i < 8; i++) {
        int row = by * 128 + tm + i;
#pragma unroll
        for (int j = 0; j < 4; j++) {
            int col = bx * 64 + tn + j;
            float v = acc[i][j];
            if (bias) v += bias[col];
            if (mode == 1) v = fmaxf(v, 0.0f);
            else if (mode == 2) v = 1.0f / (1.0f + expf(-v));
            C[(size_t)row * N + col] = v;
        }
    }
}

// ---------------- fast activations (serial-path) ----------------
__device__ __forceinline__ float fast_sigmoid(float x) {
    return __fdividef(1.0f, 1.0f + __expf(-x));
}
__device__ __forceinline__ float fast_tanh(float x) {
    if (x >  15.0f) return  1.0f;
    if (x < -15.0f) return -1.0f;
    float t = __expf(2.0f * x);
    return __fdividef(t - 1.0f, t + 1.0f);
}

// ---------------- persistent bidirectional GRU recurrence ----------------
// (unchanged from R5 — this round's ncu measurement target at launch index 3)
__global__ __launch_bounds__(512, 1) void gru_kernel(
    const float* __restrict__ w_hh_f, const float* __restrict__ w_hh_b,
    const float* __restrict__ b_hh_f, const float* __restrict__ b_hh_b)
{
    int dir = (blockIdx.x >= BD) ? 1 : 0;
    int blk = blockIdx.x - dir * BD;
    const float* gi  = dir ? d_gi_b : d_gi_f;
    const float* whh = dir ? w_hh_b : w_hh_f;
    const float* bhh = dir ? b_hh_b : b_hh_f;
    unsigned long long* hb = &d_hbuf[dir][0][0];   // [parity][unit]

    int tid  = threadIdx.x;
    int lane = tid & 31;
    int w    = tid >> 5;
    int u    = blk * UPB + w;      // hidden unit this warp produces (0..511)
    int colbase = dir ? HID : 0;

    // register-resident recurrent weights for this unit's 3 gate rows
    float wr[16], wz[16], wn[16];
#pragma unroll
    for (int i = 0; i < 16; i++) {
        int k = lane + 32 * i;
        wr[i] = whh[(size_t)u * HID + k];
        wz[i] = whh[(size_t)(HID + u) * HID + k];
        wn[i] = whh[(size_t)(2 * HID + u) * HID + k];
    }
    float br = bhh[u], bz = bhh[HID + u], bn = bhh[2 * HID + u];
    float hp = 0.0f;   // lane0: previous h of unit u (register-resident)

    __shared__ float hsh[2][HID];   // ping-pong staging by step parity

    for (int s = 0; s < LSEQ; s++) {
        int t = dir ? (LSEQ - 1 - s) : s;
        int p = s & 1;

        // prefetch input gates early (independent of handoff)
        float ir = 0.f, iz = 0.f, inn = 0.f;
        if (lane == 0) {
            const float* g = gi + (size_t)t * G3 + u;
            ir = g[0]; iz = g[512]; inn = g[1024];
        }

        if (s == 0) {
            hsh[0][tid] = 0.0f;
        } else if (w < 8) {
            // poll 2 adjacent tagged slots: detection == delivery
            int j = (w * 32 + lane) * 2;   // 0,2,..,1022
            const unsigned long long* slot = hb + (size_t)((s - 1) & 1) * HID + j;
            unsigned long long va, vb;
            unsigned tag = (unsigned)s;
            do { ld_rlx_v2_u64(slot, va, vb); }
            while ((unsigned)(va >> 32) != tag || (unsigned)(vb >> 32) != tag);
            hsh[p][j]     = __uint_as_float((unsigned)va);
            hsh[p][j + 1] = __uint_as_float((unsigned)vb);
        }
        __syncthreads();

        // 3 dot products of length 512 (one unit per warp)
        float ar = 0.f, az = 0.f, an = 0.f;
#pragma unroll
        for (int i = 0; i < 16; i++) {
            float v = hsh[p][lane + 32 * i];
            ar = fmaf(wr[i], v, ar);
            az = fmaf(wz[i], v, az);
            an = fmaf(wn[i], v, an);
        }
#pragma unroll
        for (int off = 16; off; off >>= 1) {
            ar += __shfl_xor_sync(0xffffffffu, ar, off);
            az += __shfl_xor_sync(0xffffffffu, az, off);
            an += __shfl_xor_sync(0xffffffffu, an, off);
        }

        if (lane == 0) {
            float r = fast_sigmoid(ir + ar + br);
            float z = fast_sigmoid(iz + az + bz);
            float n = fast_tanh(inn + r * (an + bn));
            float hn = (1.0f - z) * n + z * hp;
            hp = hn;
            // publish: tag s+1 + value in one atomic 8-byte relaxed store
            unsigned long long pay =
                ((unsigned long long)(unsigned)(s + 1) << 32) | (unsigned long long)__float_as_uint(hn);
            st_rlx64(hb + (size_t)p * HID + u, pay);
            d_xcat[(size_t)t * 1024 + colbase + u] = hn;
        }
        // no trailing syncthreads: leading bar + parity ping-pong + tag-gated
        // cross-block progress make smem reuse safe
    }
}

// ---------------- y[o] = sum_n a2[n][o] * p[n] ----------------
__global__ void colreduce_kernel(const float* __restrict__ A, const float* __restrict__ p,
                                 float* __restrict__ y) {
    int o = blockIdx.x * blockDim.x + threadIdx.x;   // 0..511
    float acc = 0.0f;
#pragma unroll 8
    for (int n = 0; n < LSEQ; n++)
        acc = fmaf(A[(size_t)n * 512 + o], p[n], acc);
    y[o] = acc;
}

// ---------------- launch ----------------
extern "C" void kernel_launch(void* const* d_in, const int* in_sizes, int n_in,
                              void* d_out, int out_size) {
    const float* h        = (const float*)d_in[0];
    const float* p        = (const float*)d_in[1];
    const float* w_ih_f   = (const float*)d_in[2];
    const float* w_hh_f   = (const float*)d_in[3];
    const float* b_ih_f   = (const float*)d_in[4];
    const float* b_hh_f   = (const float*)d_in[5];
    const float* w_ih_b   = (const float*)d_in[6];
    const float* w_hh_b   = (const float*)d_in[7];
    const float* b_ih_b   = (const float*)d_in[8];
    const float* b_hh_b   = (const float*)d_in[9];
    const float* base_w1  = (const float*)d_in[10];
    const float* spline_w1= (const float*)d_in[11];
    const float* scaler1  = (const float*)d_in[12];
    const float* base_w2  = (const float*)d_in[13];
    const float* spline_w2= (const float*)d_in[14];
    const float* scaler2  = (const float*)d_in[15];
    float* out = (float*)d_out;

    float *p_gi_f, *p_gi_b, *p_xcat, *p_F, *p_Wk1, *p_Wk2, *p_wihT_f, *p_wihT_b, *p_a2;
    cudaGetSymbolAddress((void**)&p_gi_f,   d_gi_f);
    cudaGetSymbolAddress((void**)&p_gi_b,   d_gi_b);
    cudaGetSymbolAddress((void**)&p_xcat,   d_xcat);
    cudaGetSymbolAddress((void**)&p_F,      d_F);
    cudaGetSymbolAddress((void**)&p_Wk1,    d_Wk1);
    cudaGetSymbolAddress((void**)&p_Wk2,    d_Wk2);
    cudaGetSymbolAddress((void**)&p_wihT_f, d_wihT_f);
    cudaGetSymbolAddress((void**)&p_wihT_b, d_wihT_b);
    cudaGetSymbolAddress((void**)&p_a2,     d_a2);

    // ncu empirically profiles launch index 3 -> gru_kernel placed there

    // 0. combined prep: reset hbuf + transpose both input-gate weight matrices
    {
        int total = 2 * G3 * INF;
        prep_kernel<<<(total + 255) / 256, 256>>>(w_ih_f, w_ih_b, p_wihT_f, p_wihT_b);
    }

    // 1,2. input-gate GEMMs: gi = h @ w_ih^T + b_ih   (4096 x 1536)
    {
        dim3 grid(G3 / 64, LSEQ / 128);
        sgemm_kernel<<<grid, 256>>>(h, p_wihT_f, p_gi_f, b_ih_f, LSEQ, G3, INF, 0);
        sgemm_kernel<<<grid, 256>>>(h, p_wihT_b, p_gi_b, b_ih_b, LSEQ, G3, INF, 0);
    }

    // 3. persistent bidirectional recurrence -> d_xcat (4096 x 1024)   [ncu target]
    gru_kernel<<<2 * BD, 512>>>(w_hh_f, w_hh_b, b_hh_f, b_hh_b);

    // 4,5. pack KAN weights
    {
        int t1 = 1024 * 9 * 512;
        int t2 = 512 * 9 * 512;
        pack_kan_kernel<<<(t1 + 255) / 256, 256>>>(base_w1, spline_w1, scaler1, p_Wk1, 1024);
        pack_kan_kernel<<<(t2 + 255) / 256, 256>>>(base_w2, spline_w2, scaler2, p_Wk2, 512);
    }

    // 6,7. KAN layer 1: features of xcat -> GEMM (+relu) -> a_1 (stored in d_out+512)
    {
        int total = LSEQ * 1024;
        featgen_kernel<<<(total + 255) / 256, 256>>>(p_xcat, p_F, total);
        dim3 grid(512 / 64, LSEQ / 128);
        sgemm_kernel<<<grid, 256>>>(p_F, p_Wk1, out + 512, nullptr, LSEQ, 512, K1DIM, 1);
    }

    // 8,9. KAN layer 2: features of a_1 -> GEMM (+sigmoid) -> a_2
    {
        int total = LSEQ * 512;
        featgen_kernel<<<(total + 255) / 256, 256>>>(out + 512, p_F, total);
        dim3 grid(512 / 64, LSEQ / 128);
        sgemm_kernel<<<grid, 256>>>(p_F, p_Wk2, p_a2, nullptr, LSEQ, 512, K2DIM, 2);
    }

    // 10. y = a_2^T @ p  (512,)
    colreduce_kernel<<<4, 128>>>(p_a2, p, out);
}